// round 4
// baseline (speedup 1.0000x reference)
#include <cuda_runtime.h>

// ---------------- f32x2 packed helpers (sm_103a) ----------------
__device__ __forceinline__ unsigned long long f2_pack(float x, float y) {
    unsigned long long u;
    asm("mov.b64 %0, {%1,%2};" : "=l"(u) : "f"(x), "f"(y));
    return u;
}
__device__ __forceinline__ unsigned long long f2_of(float2 v) { return f2_pack(v.x, v.y); }
__device__ __forceinline__ float2 f2_unpack(unsigned long long u) {
    float2 r;
    asm("mov.b64 {%0,%1}, %2;" : "=f"(r.x), "=f"(r.y) : "l"(u));
    return r;
}
__device__ __forceinline__ unsigned long long ffma2(unsigned long long a, unsigned long long b,
                                                    unsigned long long c) {
    unsigned long long d;
    asm("fma.rn.f32x2 %0, %1, %2, %3;" : "=l"(d) : "l"(a), "l"(b), "l"(c));
    return d;
}
__device__ __forceinline__ unsigned long long fadd2(unsigned long long a, unsigned long long b) {
    unsigned long long d;
    asm("add.rn.f32x2 %0, %1, %2;" : "=l"(d) : "l"(a), "l"(b));
    return d;
}

// ---------------- scratch (no allocations allowed) ----------------
__device__ __align__(16) float g_pool1[512 * 20 * 12 * 12];
__device__ __align__(16) float g_feats[512 * 640];
__device__ __align__(16) float g_M[512 * 1024];
__device__ __align__(16) float g_close[4][512 * 64];   // MBD partials (j-quarters)

// ================= Kernel 1: conv1 (1->20, 5x5) + relu + maxpool2, f32x2-packed ==========
__global__ __launch_bounds__(256) void conv1_kernel(const float* __restrict__ x,
                                                    const float* __restrict__ w,
                                                    const float* __restrict__ bias) {
    __shared__ __align__(16) float sx[784];
    __shared__ __align__(16) float2 sw2[500];   // duplicated (w,w) pairs
    __shared__ float sb[20];
    const int b = blockIdx.x, tid = threadIdx.x;
    const float* xb = x + b * 784;
    for (int i = tid; i < 784; i += 256) sx[i] = xb[i];
    for (int i = tid; i < 500; i += 256) { float v = w[i]; sw2[i] = make_float2(v, v); }
    if (tid < 20) sb[tid] = bias[tid];
    __syncthreads();

    for (int o = tid; o < 2880; o += 256) {
        const int oc = o / 144, p = o % 144;
        const int oy = p / 12, ox = p % 12;
        const int r0 = oy * 2, c0 = ox * 2;
        const float* ip = &sx[r0 * 28 + c0];

        unsigned long long A0 = 0ull, A1 = 0ull;   // (a00,a01), (a10,a11)
        unsigned long long rp0[5], rp1[5];
        // build row-0 packs: shifted pairs come from contiguous float2 loads
        {
            float2 p0 = *(const float2*)(ip + 0), p1 = *(const float2*)(ip + 2),
                   p2 = *(const float2*)(ip + 4);
            rp0[0] = f2_of(p0); rp0[2] = f2_of(p1); rp0[4] = f2_of(p2);
            rp0[1] = f2_pack(p0.y, p1.x); rp0[3] = f2_pack(p1.y, p2.x);
        }
        const float2* wp = &sw2[oc * 25];
#pragma unroll
        for (int ky = 0; ky < 5; ky++) {
            const float* rb = ip + (ky + 1) * 28;
            float2 p0 = *(const float2*)(rb + 0), p1 = *(const float2*)(rb + 2),
                   p2 = *(const float2*)(rb + 4);
            rp1[0] = f2_of(p0); rp1[2] = f2_of(p1); rp1[4] = f2_of(p2);
            rp1[1] = f2_pack(p0.y, p1.x); rp1[3] = f2_pack(p1.y, p2.x);
#pragma unroll
            for (int kx = 0; kx < 5; kx++) {
                const unsigned long long wv = f2_of(wp[ky * 5 + kx]);
                A0 = ffma2(rp0[kx], wv, A0);
                A1 = ffma2(rp1[kx], wv, A1);
            }
#pragma unroll
            for (int q = 0; q < 5; q++) rp0[q] = rp1[q];
        }
        float2 a0 = f2_unpack(A0), a1 = f2_unpack(A1);
        float m = fmaxf(fmaxf(a0.x, a0.y), fmaxf(a1.x, a1.y));
        g_pool1[b * 2880 + o] = fmaxf(m + sb[oc], 0.f);
    }
}

// ================= Kernel 2: conv2 (20->40, 5x5) + relu + maxpool2, f32x2-packed =========
// 320 threads: g = tid/16 handles oc {g, g+20}; p = tid%16 is pool position.
__global__ __launch_bounds__(320) void conv2_kernel(const float* __restrict__ w,
                                                    const float* __restrict__ bias) {
    __shared__ __align__(16) float s_in[2880];
    __shared__ __align__(16) float2 sw2[2][1000];  // duplicated (w,w), double-buffered per ic
    __shared__ float sb[40];
    const int b = blockIdx.x, tid = threadIdx.x;
    for (int i = tid; i < 2880; i += 320) s_in[i] = g_pool1[b * 2880 + i];
    if (tid < 40) sb[tid] = bias[tid];
    for (int i = tid; i < 1000; i += 320) {
        const int oc = i / 25, t = i % 25;
        float v = w[oc * 500 + t];           // ic = 0
        sw2[0][i] = make_float2(v, v);
    }
    __syncthreads();

    const int g = tid / 16;
    const int p = tid % 16;
    const int oy = p / 4, ox = p % 4;
    const int r0 = oy * 2, c0 = ox * 2;

    unsigned long long A0 = 0ull, A1 = 0ull;   // oc = g     : (a00,a01),(a10,a11)
    unsigned long long B0 = 0ull, B1 = 0ull;   // oc = g+20

    for (int ic = 0; ic < 20; ic++) {
        const int cur = ic & 1, nxt = cur ^ 1;
        if (ic < 19) {
            for (int i = tid; i < 1000; i += 320) {
                const int oc = i / 25, t = i % 25;
                float v = w[oc * 500 + (ic + 1) * 25 + t];
                sw2[nxt][i] = make_float2(v, v);
            }
        }
        const float* ip = &s_in[ic * 144 + r0 * 12 + c0];
        unsigned long long rp0[5], rp1[5];
        {
            float2 p0 = *(const float2*)(ip + 0), p1 = *(const float2*)(ip + 2),
                   p2 = *(const float2*)(ip + 4);
            rp0[0] = f2_of(p0); rp0[2] = f2_of(p1); rp0[4] = f2_of(p2);
            rp0[1] = f2_pack(p0.y, p1.x); rp0[3] = f2_pack(p1.y, p2.x);
        }
        const float2* w0 = &sw2[cur][g * 25];
        const float2* w1 = &sw2[cur][(g + 20) * 25];
#pragma unroll
        for (int ky = 0; ky < 5; ky++) {
            const float* rb = ip + (ky + 1) * 12;
            float2 p0 = *(const float2*)(rb + 0), p1 = *(const float2*)(rb + 2),
                   p2 = *(const float2*)(rb + 4);
            rp1[0] = f2_of(p0); rp1[2] = f2_of(p1); rp1[4] = f2_of(p2);
            rp1[1] = f2_pack(p0.y, p1.x); rp1[3] = f2_pack(p1.y, p2.x);
#pragma unroll
            for (int kx = 0; kx < 5; kx++) {
                const unsigned long long wa = f2_of(w0[ky * 5 + kx]);
                const unsigned long long wb = f2_of(w1[ky * 5 + kx]);
                A0 = ffma2(rp0[kx], wa, A0);
                A1 = ffma2(rp1[kx], wa, A1);
                B0 = ffma2(rp0[kx], wb, B0);
                B1 = ffma2(rp1[kx], wb, B1);
            }
#pragma unroll
            for (int q = 0; q < 5; q++) rp0[q] = rp1[q];
        }
        __syncthreads();
    }
    float2 a0 = f2_unpack(A0), a1 = f2_unpack(A1);
    float m0 = fmaxf(fmaxf(a0.x, a0.y), fmaxf(a1.x, a1.y));
    g_feats[b * 640 + g * 16 + p] = fmaxf(m0 + sb[g], 0.f);
    float2 b0v = f2_unpack(B0), b1v = f2_unpack(B1);
    float m1 = fmaxf(fmaxf(b0v.x, b0v.y), fmaxf(b1v.x, b1v.y));
    g_feats[b * 640 + (g + 20) * 16 + p] = fmaxf(m1 + sb[g + 20], 0.f);
}

// ================= Kernel 3: M = feats[512,640] @ T^T  (T:[1024,640]) =================
// BM=64, BN=64, BK=16, 256 threads, 4x4 microtile. As transposed (pad 68) for LDS.128.
__global__ __launch_bounds__(256) void gemmT_kernel(const float* __restrict__ T) {
    __shared__ __align__(16) float As[16 * 68];
    __shared__ float Bs[64 * 17];
    const int tx = threadIdx.x & 15, ty = threadIdx.x >> 4;
    const int i0 = blockIdx.y * 64, j0 = blockIdx.x * 64;
    const int lrow = threadIdx.x >> 2, lkq = threadIdx.x & 3;
    float acc[4][4] = {};

    for (int k0 = 0; k0 < 640; k0 += 16) {
        __syncthreads();
        float4 va = *(const float4*)&g_feats[(i0 + lrow) * 640 + k0 + lkq * 4];
        As[(lkq * 4 + 0) * 68 + lrow] = va.x;
        As[(lkq * 4 + 1) * 68 + lrow] = va.y;
        As[(lkq * 4 + 2) * 68 + lrow] = va.z;
        As[(lkq * 4 + 3) * 68 + lrow] = va.w;
        float4 vb = *(const float4*)&T[(j0 + lrow) * 640 + k0 + lkq * 4];
        Bs[lrow * 17 + lkq * 4 + 0] = vb.x;
        Bs[lrow * 17 + lkq * 4 + 1] = vb.y;
        Bs[lrow * 17 + lkq * 4 + 2] = vb.z;
        Bs[lrow * 17 + lkq * 4 + 3] = vb.w;
        __syncthreads();
#pragma unroll
        for (int kk = 0; kk < 16; kk++) {
            float4 av = *(const float4*)&As[kk * 68 + ty * 4];
            float a[4] = {av.x, av.y, av.z, av.w};
            float bb[4];
#pragma unroll
            for (int n = 0; n < 4; n++) bb[n] = Bs[(tx + 16 * n) * 17 + kk];
#pragma unroll
            for (int m = 0; m < 4; m++)
#pragma unroll
                for (int n = 0; n < 4; n++) acc[m][n] += a[m] * bb[n];
        }
    }
#pragma unroll
    for (int m = 0; m < 4; m++)
#pragma unroll
        for (int n = 0; n < 4; n++)
            g_M[(i0 + ty * 4 + m) * 1024 + j0 + tx + 16 * n] = acc[m][n];
}

// ================= Kernel 4: minibatch discrimination, packed f32x2 =================
// closeness[i,b] = sum_j exp(-sum_c |M[i,b,c]-M[j,b,c]|)
// grid (4 i-tiles, 64 b-slots, 4 j-quarters); |a-r| = (r + (-a)) & 0x7FFF... (add on
// fma pipe, mask on alu pipe -> dual-issue). Each quarter writes its own partial
// buffer: fixed summation order in fc_kernel -> deterministic, no atomics.
__global__ __launch_bounds__(128) void mbd_kernel() {
    __shared__ __align__(16) float sj[128 * 16];
    const int bslot = blockIdx.y;
    const int quarter = blockIdx.z;
    const int i = blockIdx.x * 128 + threadIdx.x;
    const int jbase = quarter * 128;

    // own row, negated & packed: na[k] = (-a[2k], -a[2k+1])
    unsigned long long na[8];
    {
        const ulonglong2* mp = (const ulonglong2*)&g_M[i * 1024 + bslot * 16];
#pragma unroll
        for (int q = 0; q < 4; q++) {
            ulonglong2 v = mp[q];
            na[2 * q + 0] = v.x ^ 0x8000000080000000ull;
            na[2 * q + 1] = v.y ^ 0x8000000080000000ull;
        }
    }
    // stage this quarter's 128x16 j-tile
#pragma unroll
    for (int t = 0; t < 4; t++) {
        const int v = threadIdx.x + t * 128;
        const int row = v >> 2, cq = v & 3;
        *(float4*)&sj[row * 16 + cq * 4] =
            *(const float4*)&g_M[(jbase + row) * 1024 + bslot * 16 + cq * 4];
    }
    __syncthreads();

    const unsigned long long ABSM = 0x7FFFFFFF7FFFFFFFull;
    float acc = 0.f;
#pragma unroll 4
    for (int jj = 0; jj < 128; jj++) {
        const ulonglong2* rr = (const ulonglong2*)&sj[jj * 16];
        unsigned long long d0 = 0ull, d1 = 0ull;
#pragma unroll
        for (int q = 0; q < 4; q++) {
            ulonglong2 v = rr[q];
            unsigned long long t0 = fadd2(na[2 * q + 0], v.x) & ABSM;
            unsigned long long t1 = fadd2(na[2 * q + 1], v.y) & ABSM;
            d0 = fadd2(d0, t0);
            d1 = fadd2(d1, t1);
        }
        float2 s = f2_unpack(fadd2(d0, d1));
        acc += __expf(-(s.x + s.y));
    }
    g_close[quarter][i * 64 + bslot] = acc;
}

// ================= Kernel 5: fc1 (704->100) + relu + fc2 (100->1) + sigmoid =============
// 4 images per block, 128 blocks, 128 threads.
__global__ __launch_bounds__(128) void fc_kernel(const float* __restrict__ w1,
                                                 const float* __restrict__ b1,
                                                 const float* __restrict__ w2,
                                                 const float* __restrict__ b2,
                                                 float* __restrict__ out) {
    __shared__ __align__(16) float sin_t[704 * 4];
    __shared__ float wtile[100 * 33];
    __shared__ float shid[100 * 4];
    const int b0 = blockIdx.x * 4;
    const int tid = threadIdx.x;

    for (int idx = tid; idx < 704 * 4; idx += 128) {
        const int c = idx >> 2, img = idx & 3;
        float v;
        if (c < 640) {
            v = g_feats[(b0 + img) * 640 + c];
        } else {
            const int cc = (b0 + img) * 64 + (c - 640);
            v = (g_close[0][cc] + g_close[1][cc]) + (g_close[2][cc] + g_close[3][cc]);
        }
        sin_t[c * 4 + img] = v;
    }

    float acc[4];
    const int k = tid;
    if (k < 100) {
        const float bb = b1[k];
#pragma unroll
        for (int m = 0; m < 4; m++) acc[m] = bb;
    }
    for (int c0 = 0; c0 < 704; c0 += 32) {
        __syncthreads();
        for (int idx = tid; idx < 3200; idx += 128) {
            const int kk = idx >> 5, cc = idx & 31;
            wtile[kk * 33 + cc] = w1[kk * 704 + c0 + cc];
        }
        __syncthreads();
        if (k < 100) {
#pragma unroll 8
            for (int cc = 0; cc < 32; cc++) {
                const float wv = wtile[k * 33 + cc];
                const float4 ip = *(const float4*)&sin_t[(c0 + cc) * 4];
                acc[0] += wv * ip.x; acc[1] += wv * ip.y;
                acc[2] += wv * ip.z; acc[3] += wv * ip.w;
            }
        }
    }
    if (k < 100) {
#pragma unroll
        for (int m = 0; m < 4; m++) shid[k * 4 + m] = fmaxf(acc[m], 0.f);
    }
    __syncthreads();

    // fc2: one warp per image
    const int img = tid >> 5, lane = tid & 31;
    float s = 0.f;
    for (int kk = lane; kk < 100; kk += 32) s += shid[kk * 4 + img] * w2[kk];
#pragma unroll
    for (int off = 16; off; off >>= 1) s += __shfl_down_sync(0xffffffffu, s, off);
    if (lane == 0) {
        const float z = s + b2[0];
        out[b0 + img] = 1.f / (1.f + __expf(-z));
    }
}

// ================= launch =================
extern "C" void kernel_launch(void* const* d_in, const int* in_sizes, int n_in,
                              void* d_out, int out_size) {
    const float* x     = (const float*)d_in[0];
    const float* c1w   = (const float*)d_in[1];
    const float* c1b   = (const float*)d_in[2];
    const float* c2w   = (const float*)d_in[3];
    const float* c2b   = (const float*)d_in[4];
    const float* Tm    = (const float*)d_in[5];
    const float* fc1w  = (const float*)d_in[6];
    const float* fc1b  = (const float*)d_in[7];
    const float* fc2w  = (const float*)d_in[8];
    const float* fc2b  = (const float*)d_in[9];
    float* out = (float*)d_out;

    conv1_kernel<<<512, 256>>>(x, c1w, c1b);
    conv2_kernel<<<512, 320>>>(c2w, c2b);
    gemmT_kernel<<<dim3(16, 8), 256>>>(Tm);
    mbd_kernel<<<dim3(4, 64, 4), 128>>>();
    fc_kernel<<<128, 128>>>(fc1w, fc1b, fc2w, fc2b, out);
}

// round 13
// speedup vs baseline: 1.0207x; 1.0207x over previous
#include <cuda_runtime.h>

// ---------------- f32x2 packed helpers (conv kernels) ----------------
__device__ __forceinline__ unsigned long long f2_pack(float x, float y) {
    unsigned long long u;
    asm("mov.b64 %0, {%1,%2};" : "=l"(u) : "f"(x), "f"(y));
    return u;
}
__device__ __forceinline__ unsigned long long f2_of(float2 v) { return f2_pack(v.x, v.y); }
__device__ __forceinline__ float2 f2_unpack(unsigned long long u) {
    float2 r;
    asm("mov.b64 {%0,%1}, %2;" : "=f"(r.x), "=f"(r.y) : "l"(u));
    return r;
}
__device__ __forceinline__ unsigned long long ffma2(unsigned long long a, unsigned long long b,
                                                    unsigned long long c) {
    unsigned long long d;
    asm("fma.rn.f32x2 %0, %1, %2, %3;" : "=l"(d) : "l"(a), "l"(b), "l"(c));
    return d;
}

// ---------------- scratch (no allocations allowed) ----------------
__device__ __align__(16) float g_pool1[512 * 20 * 12 * 12];
__device__ __align__(16) float g_feats[512 * 640];
__device__ __align__(16) float g_M[512 * 1024];
__device__ __align__(16) float g_close8[8][512 * 64];   // MBD partials per 64-row j-tile

// ================= Kernel 1: conv1 (1->20, 5x5) + relu + maxpool2 ==========
__global__ __launch_bounds__(256) void conv1_kernel(const float* __restrict__ x,
                                                    const float* __restrict__ w,
                                                    const float* __restrict__ bias) {
    __shared__ __align__(16) float sx[784];
    __shared__ __align__(16) float2 sw2[500];
    __shared__ float sb[20];
    const int b = blockIdx.x, tid = threadIdx.x;
    const float* xb = x + b * 784;
    for (int i = tid; i < 784; i += 256) sx[i] = xb[i];
    for (int i = tid; i < 500; i += 256) { float v = w[i]; sw2[i] = make_float2(v, v); }
    if (tid < 20) sb[tid] = bias[tid];
    __syncthreads();

    for (int o = tid; o < 2880; o += 256) {
        const int oc = o / 144, p = o % 144;
        const int oy = p / 12, ox = p % 12;
        const float* ip = &sx[oy * 2 * 28 + ox * 2];
        unsigned long long A0 = 0ull, A1 = 0ull;
        unsigned long long rp0[5], rp1[5];
        {
            float2 p0 = *(const float2*)(ip + 0), p1 = *(const float2*)(ip + 2),
                   p2 = *(const float2*)(ip + 4);
            rp0[0] = f2_of(p0); rp0[2] = f2_of(p1); rp0[4] = f2_of(p2);
            rp0[1] = f2_pack(p0.y, p1.x); rp0[3] = f2_pack(p1.y, p2.x);
        }
        const float2* wp = &sw2[oc * 25];
#pragma unroll
        for (int ky = 0; ky < 5; ky++) {
            const float* rb = ip + (ky + 1) * 28;
            float2 p0 = *(const float2*)(rb + 0), p1 = *(const float2*)(rb + 2),
                   p2 = *(const float2*)(rb + 4);
            rp1[0] = f2_of(p0); rp1[2] = f2_of(p1); rp1[4] = f2_of(p2);
            rp1[1] = f2_pack(p0.y, p1.x); rp1[3] = f2_pack(p1.y, p2.x);
#pragma unroll
            for (int kx = 0; kx < 5; kx++) {
                const unsigned long long wv = f2_of(wp[ky * 5 + kx]);
                A0 = ffma2(rp0[kx], wv, A0);
                A1 = ffma2(rp1[kx], wv, A1);
            }
#pragma unroll
            for (int q = 0; q < 5; q++) rp0[q] = rp1[q];
        }
        float2 a0 = f2_unpack(A0), a1 = f2_unpack(A1);
        float m = fmaxf(fmaxf(a0.x, a0.y), fmaxf(a1.x, a1.y));
        g_pool1[b * 2880 + o] = fmaxf(m + sb[oc], 0.f);
    }
}

// ================= Kernel 2: conv2 (20->40, 5x5) + relu + maxpool2 =========
__global__ __launch_bounds__(320) void conv2_kernel(const float* __restrict__ w,
                                                    const float* __restrict__ bias) {
    __shared__ __align__(16) float s_in[2880];
    __shared__ __align__(16) float2 sw2[2][1000];
    __shared__ float sb[40];
    const int b = blockIdx.x, tid = threadIdx.x;
    for (int i = tid; i < 2880; i += 320) s_in[i] = g_pool1[b * 2880 + i];
    if (tid < 40) sb[tid] = bias[tid];
    for (int i = tid; i < 1000; i += 320) {
        const int oc = i / 25, t = i % 25;
        float v = w[oc * 500 + t];
        sw2[0][i] = make_float2(v, v);
    }
    __syncthreads();

    const int g = tid / 16, p = tid % 16;
    const int r0 = (p / 4) * 2, c0 = (p % 4) * 2;
    unsigned long long A0 = 0ull, A1 = 0ull, B0 = 0ull, B1 = 0ull;

    for (int ic = 0; ic < 20; ic++) {
        const int cur = ic & 1, nxt = cur ^ 1;
        if (ic < 19) {
            for (int i = tid; i < 1000; i += 320) {
                const int oc = i / 25, t = i % 25;
                float v = w[oc * 500 + (ic + 1) * 25 + t];
                sw2[nxt][i] = make_float2(v, v);
            }
        }
        const float* ip = &s_in[ic * 144 + r0 * 12 + c0];
        unsigned long long rp0[5], rp1[5];
        {
            float2 p0 = *(const float2*)(ip + 0), p1 = *(const float2*)(ip + 2),
                   p2 = *(const float2*)(ip + 4);
            rp0[0] = f2_of(p0); rp0[2] = f2_of(p1); rp0[4] = f2_of(p2);
            rp0[1] = f2_pack(p0.y, p1.x); rp0[3] = f2_pack(p1.y, p2.x);
        }
        const float2* w0 = &sw2[cur][g * 25];
        const float2* w1 = &sw2[cur][(g + 20) * 25];
#pragma unroll
        for (int ky = 0; ky < 5; ky++) {
            const float* rb = ip + (ky + 1) * 12;
            float2 p0 = *(const float2*)(rb + 0), p1 = *(const float2*)(rb + 2),
                   p2 = *(const float2*)(rb + 4);
            rp1[0] = f2_of(p0); rp1[2] = f2_of(p1); rp1[4] = f2_of(p2);
            rp1[1] = f2_pack(p0.y, p1.x); rp1[3] = f2_pack(p1.y, p2.x);
#pragma unroll
            for (int kx = 0; kx < 5; kx++) {
                const unsigned long long wa = f2_of(w0[ky * 5 + kx]);
                const unsigned long long wb = f2_of(w1[ky * 5 + kx]);
                A0 = ffma2(rp0[kx], wa, A0);
                A1 = ffma2(rp1[kx], wa, A1);
                B0 = ffma2(rp0[kx], wb, B0);
                B1 = ffma2(rp1[kx], wb, B1);
            }
#pragma unroll
            for (int q = 0; q < 5; q++) rp0[q] = rp1[q];
        }
        __syncthreads();
    }
    float2 a0 = f2_unpack(A0), a1 = f2_unpack(A1);
    g_feats[b * 640 + g * 16 + p] =
        fmaxf(fmaxf(fmaxf(a0.x, a0.y), fmaxf(a1.x, a1.y)) + sb[g], 0.f);
    float2 b0v = f2_unpack(B0), b1v = f2_unpack(B1);
    g_feats[b * 640 + (g + 20) * 16 + p] =
        fmaxf(fmaxf(fmaxf(b0v.x, b0v.y), fmaxf(b1v.x, b1v.y)) + sb[g + 20], 0.f);
}

// ================= Kernel 3: M = feats[512,640] @ T^T  (T:[1024,640]) =================
// BM=64, BN=64, BK=16, 256 threads, 4x4 microtile. As transposed (pad 68) for LDS.128.
__global__ __launch_bounds__(256) void gemmT_kernel(const float* __restrict__ T) {
    __shared__ __align__(16) float As[16 * 68];
    __shared__ float Bs[64 * 17];
    const int tx = threadIdx.x & 15, ty = threadIdx.x >> 4;
    const int i0 = blockIdx.y * 64, j0 = blockIdx.x * 64;
    const int lrow = threadIdx.x >> 2, lkq = threadIdx.x & 3;
    float acc[4][4] = {};

    for (int k0 = 0; k0 < 640; k0 += 16) {
        __syncthreads();
        float4 va = *(const float4*)&g_feats[(i0 + lrow) * 640 + k0 + lkq * 4];
        As[(lkq * 4 + 0) * 68 + lrow] = va.x;
        As[(lkq * 4 + 1) * 68 + lrow] = va.y;
        As[(lkq * 4 + 2) * 68 + lrow] = va.z;
        As[(lkq * 4 + 3) * 68 + lrow] = va.w;
        float4 vb = *(const float4*)&T[(j0 + lrow) * 640 + k0 + lkq * 4];
        Bs[lrow * 17 + lkq * 4 + 0] = vb.x;
        Bs[lrow * 17 + lkq * 4 + 1] = vb.y;
        Bs[lrow * 17 + lkq * 4 + 2] = vb.z;
        Bs[lrow * 17 + lkq * 4 + 3] = vb.w;
        __syncthreads();
#pragma unroll
        for (int kk = 0; kk < 16; kk++) {
            float4 av = *(const float4*)&As[kk * 68 + ty * 4];
            float a[4] = {av.x, av.y, av.z, av.w};
            float bb[4];
#pragma unroll
            for (int n = 0; n < 4; n++) bb[n] = Bs[(tx + 16 * n) * 17 + kk];
#pragma unroll
            for (int m = 0; m < 4; m++)
#pragma unroll
                for (int n = 0; n < 4; n++) acc[m][n] += a[m] * bb[n];
        }
    }
#pragma unroll
    for (int m = 0; m < 4; m++)
#pragma unroll
        for (int n = 0; n < 4; n++)
            g_M[(i0 + ty * 4 + m) * 1024 + j0 + tx + 16 * n] = acc[m][n];
}

// ================= Kernel 4: minibatch discrimination, SYMMETRIC tiles =================
// dist(i,j)=dist(j,i): compute each unordered pair once on 64x64 triangular tiles.
// Off-diag tile (ti<tj): stage exp values in smem E, emit row sums -> partial[tj][rows ti]
// and column sums -> partial[ti][rows tj]. Diagonal tile: row sums only (incl. j==i).
// Each (buffer q, row-block p) written by exactly one tile (min(p,q),max(p,q)) -> deterministic.
__global__ __launch_bounds__(128) void mbd_sym_kernel() {
    __shared__ __align__(16) float MJ[64 * 16];
    __shared__ float E[64 * 65];
    const int bslot = blockIdx.y;
    // decode triangular tile 0..35 -> (ti, tj), ti <= tj
    int lin = blockIdx.x, ti = 0, rowlen = 8;
    while (lin >= rowlen) { lin -= rowlen; ti++; rowlen--; }
    const int tj = ti + lin;
    const bool diag = (ti == tj);

    const int t = threadIdx.x;
    const int irow = t >> 1;          // 0..63 (each row handled by 2 threads)
    const int jhalf = (t & 1) * 32;   // each thread covers 32 j

    // own row (ti*64 + irow) in registers
    float a[16];
    {
        const float* mp = &g_M[(ti * 64 + irow) * 1024 + bslot * 16];
#pragma unroll
        for (int q = 0; q < 4; q++) {
            float4 v = *(const float4*)&mp[q * 4];
            a[q * 4] = v.x; a[q * 4 + 1] = v.y; a[q * 4 + 2] = v.z; a[q * 4 + 3] = v.w;
        }
    }
    // stage J-tile rows (tj*64 .. +63): 256 float4, 2 per thread
#pragma unroll
    for (int s = 0; s < 2; s++) {
        const int v4 = t + s * 128;
        const int row = v4 >> 2, cq = v4 & 3;
        *(float4*)&MJ[row * 16 + cq * 4] =
            *(const float4*)&g_M[(tj * 64 + row) * 1024 + bslot * 16 + cq * 4];
    }
    __syncthreads();

    float accI = 0.f;
#pragma unroll 2
    for (int jj = 0; jj < 32; jj++) {
        const float* r = &MJ[(jhalf + jj) * 16];
        float d = 0.f;
#pragma unroll
        for (int c = 0; c < 16; c++) d += fabsf(a[c] - r[c]);
        const float e = __expf(-d);
        accI += e;
        if (!diag) E[irow * 65 + jhalf + jj] = e;
    }
    accI += __shfl_xor_sync(0xffffffffu, accI, 1);
    if ((t & 1) == 0)
        g_close8[tj][(ti * 64 + irow) * 64 + bslot] = accI;

    if (!diag) {
        __syncthreads();
        // column sums: thread t handles column j = t>>1 over i-range (t&1)*32..+31
        const int jcol = t >> 1;
        const int ihalf = (t & 1) * 32;
        float accJ = 0.f;
#pragma unroll 4
        for (int s = 0; s < 32; s++)
            accJ += E[(ihalf + s) * 65 + jcol];
        accJ += __shfl_xor_sync(0xffffffffu, accJ, 1);
        if ((t & 1) == 0)
            g_close8[ti][(tj * 64 + jcol) * 64 + bslot] = accJ;
    }
}

// ================= Kernel 5: fc1 (704->100) + relu + fc2 (100->1) + sigmoid =============
// 4 images per block, 128 blocks, 128 threads. Closeness = fixed-order sum of 8 partials.
__global__ __launch_bounds__(128) void fc_kernel(const float* __restrict__ w1,
                                                 const float* __restrict__ b1,
                                                 const float* __restrict__ w2,
                                                 const float* __restrict__ b2,
                                                 float* __restrict__ out) {
    __shared__ __align__(16) float sin_t[704 * 4];
    __shared__ float wtile[100 * 33];
    __shared__ float shid[100 * 4];
    const int b0 = blockIdx.x * 4;
    const int tid = threadIdx.x;

    for (int idx = tid; idx < 704 * 4; idx += 128) {
        const int c = idx >> 2, img = idx & 3;
        float v;
        if (c < 640) {
            v = g_feats[(b0 + img) * 640 + c];
        } else {
            const int cc = (b0 + img) * 64 + (c - 640);
            v = ((g_close8[0][cc] + g_close8[1][cc]) + (g_close8[2][cc] + g_close8[3][cc]))
              + ((g_close8[4][cc] + g_close8[5][cc]) + (g_close8[6][cc] + g_close8[7][cc]));
        }
        sin_t[c * 4 + img] = v;
    }

    float acc[4];
    const int k = tid;
    if (k < 100) {
        const float bb = b1[k];
#pragma unroll
        for (int m = 0; m < 4; m++) acc[m] = bb;
    }
    for (int c0 = 0; c0 < 704; c0 += 32) {
        __syncthreads();
        for (int idx = tid; idx < 3200; idx += 128) {
            const int kk = idx >> 5, cc = idx & 31;
            wtile[kk * 33 + cc] = w1[kk * 704 + c0 + cc];
        }
        __syncthreads();
        if (k < 100) {
#pragma unroll 8
            for (int cc = 0; cc < 32; cc++) {
                const float wv = wtile[k * 33 + cc];
                const float4 ip = *(const float4*)&sin_t[(c0 + cc) * 4];
                acc[0] += wv * ip.x; acc[1] += wv * ip.y;
                acc[2] += wv * ip.z; acc[3] += wv * ip.w;
            }
        }
    }
    if (k < 100) {
#pragma unroll
        for (int m = 0; m < 4; m++) shid[k * 4 + m] = fmaxf(acc[m], 0.f);
    }
    __syncthreads();

    const int img = tid >> 5, lane = tid & 31;
    float s = 0.f;
    for (int kk = lane; kk < 100; kk += 32) s += shid[kk * 4 + img] * w2[kk];
#pragma unroll
    for (int off = 16; off; off >>= 1) s += __shfl_down_sync(0xffffffffu, s, off);
    if (lane == 0) {
        const float z = s + b2[0];
        out[b0 + img] = 1.f / (1.f + __expf(-z));
    }
}

// ================= launch =================
extern "C" void kernel_launch(void* const* d_in, const int* in_sizes, int n_in,
                              void* d_out, int out_size) {
    const float* x    = (const float*)d_in[0];
    const float* c1w  = (const float*)d_in[1];
    const float* c1b  = (const float*)d_in[2];
    const float* c2w  = (const float*)d_in[3];
    const float* c2b  = (const float*)d_in[4];
    const float* Tm   = (const float*)d_in[5];
    const float* fc1w = (const float*)d_in[6];
    const float* fc1b = (const float*)d_in[7];
    const float* fc2w = (const float*)d_in[8];
    const float* fc2b = (const float*)d_in[9];
    float* out = (float*)d_out;

    conv1_kernel<<<512, 256>>>(x, c1w, c1b);
    conv2_kernel<<<512, 320>>>(c2w, c2b);
    gemmT_kernel<<<dim3(16, 8), 256>>>(Tm);
    mbd_sym_kernel<<<dim3(36, 64), 128>>>();
    fc_kernel<<<128, 128>>>(fc1w, fc1b, fc2w, fc2b, out);
}